// round 13
// baseline (speedup 1.0000x reference)
#include <cuda_runtime.h>

#define BB 64
#define SS 4096
#define DD 128
#define NPTS (BB*SS)
#define CHUNKS 16
#define PPB (SS/CHUNKS)
#define GRID_STATS 740            // 5 blocks/SM * 148 SMs, one wave
#define NW_STATS (GRID_STATS * 8)
#define GRID_FIN 592              // 4 blocks/SM * 148 SMs, one wave
#define NW_FIN (GRID_FIN * 8)

// scratch (allocation-free rule: __device__ globals)
__device__ float  g_part[CHUNKS*BB*DD]; // per-(chunk,b,d) partial sums
__device__ float4 g_mean4[DD/4];        // global Lorentz centroid
__device__ double g_fs[DD];             // per-feature sum of x_T
__device__ double g_fq[DD];             // per-feature sum of x_T^2
__device__ float4 g_scal[NPTS];         // per-point (fac, c2, coef) from k_stats

__device__ __forceinline__ float wsum(float v) {
#pragma unroll
    for (int o = 16; o; o >>= 1) v += __shfl_xor_sync(0xffffffffu, v, o);
    return v;
}

// 16-lane-segment reduction: 4 stages, reduces two points per warp at once
__device__ __forceinline__ float segsum(float v) {
#pragma unroll
    for (int o = 8; o; o >>= 1) v += __shfl_xor_sync(0xffffffffu, v, o);
    return v;
}
__device__ __forceinline__ void segsum2(float& a, float& b) {
#pragma unroll
    for (int o = 8; o; o >>= 1) {
        float ta = __shfl_xor_sync(0xffffffffu, a, o);
        float tb = __shfl_xor_sync(0xffffffffu, b, o);
        a += ta; b += tb;
    }
}
__device__ __forceinline__ float dot4(float4 a, float4 b) {
    return a.x*b.x + a.y*b.y + a.z*b.z + a.w*b.w;
}
// register-free L2 prefetch hint
__device__ __forceinline__ void pfL2(const void* p) {
    asm volatile("prefetch.global.L2 [%0];" :: "l"(p));
}

// Pass 1: per-(b,chunk) sums over 256 points -> g_part (no atomics, no init)
__global__ __launch_bounds__(256) void k_sumS(const float4* __restrict__ x4) {
    int b     = blockIdx.x >> 4;
    int chunk = blockIdx.x & 15;
    int warp = threadIdx.x >> 5, lane = threadIdx.x & 31;
    const float4* base = x4 + ((size_t)b * SS + (size_t)chunk * PPB) * 32 + lane;
    float4 acc = make_float4(0.f, 0.f, 0.f, 0.f);
#pragma unroll 4
    for (int s = warp; s < PPB; s += 8) {
        float4 v = base[(size_t)s * 32];
        acc.x += v.x; acc.y += v.y; acc.z += v.z; acc.w += v.w;
    }
    __shared__ float sh[8 * 128];
    int o = warp * 128 + lane * 4;
    sh[o] = acc.x; sh[o+1] = acc.y; sh[o+2] = acc.z; sh[o+3] = acc.w;
    __syncthreads();
    if (threadIdx.x < 128) {
        float v = 0.f;
#pragma unroll
        for (int w = 0; w < 8; w++) v += sh[w * 128 + threadIdx.x];
        g_part[(chunk * BB + b) * DD + threadIdx.x] = v;
    }
}

// Pass 2 (tiny): reduce partials, centroid of per-batch centroids, zero stats
__global__ __launch_bounds__(1024) void k_centroid() {
    __shared__ float sh1[BB * DD];
    __shared__ float red[128];
    __shared__ float s_linner;
    int tid = threadIdx.x, warp = tid >> 5, lane = tid & 31;

    for (int idx = tid; idx < BB*DD; idx += 1024) {
        float s = 0.f;
#pragma unroll
        for (int c = 0; c < CHUNKS; c++) s += g_part[c * BB * DD + idx];
        sh1[idx] = s;
    }
    if (tid < DD) { g_fs[tid] = 0.0; g_fq[tid] = 0.0; }
    __syncthreads();

#pragma unroll
    for (int rep = 0; rep < 2; rep++) {
        int b = warp + rep * 32;
        float a[4];
        float lc = 0.f;
#pragma unroll
        for (int j = 0; j < 4; j++) {
            a[j] = sh1[b * 128 + lane * 4 + j] * (1.f / SS);
            float c = a[j] * a[j];
            if (lane == 0 && j == 0) c = -c;
            lc += c;
        }
        lc = wsum(lc);
        float denom = sqrtf(fmaxf(-lc, 1e-8f));
#pragma unroll
        for (int j = 0; j < 4; j++) sh1[b * 128 + lane * 4 + j] = a[j] / denom;
    }
    __syncthreads();

    float a2 = 0.f;
    if (tid < 128) {
        float s = 0.f;
        for (int b = 0; b < BB; b++) s += sh1[b * 128 + tid];
        a2 = s * (1.f / BB);
        float c = a2 * a2;
        red[tid] = (tid == 0) ? -c : c;
    }
    __syncthreads();
    for (int off = 64; off > 0; off >>= 1) {
        if (tid < off) red[tid] += red[tid + off];
        __syncthreads();
    }
    if (tid == 0) s_linner = red[0];
    __syncthreads();
    if (tid < 128) {
        float denom2 = sqrtf(fmaxf(-s_linner, 1e-8f));
        ((float*)g_mean4)[tid] = a2 / denom2;
    }
}

// Pass 3: per-feature sum / sumsq of x_T. 16-lane segments: each half-warp
// owns one point (8 features/lane as 2 float4), 2 points per warp-iteration.
// ALSO caches (fac, c2, coef) per point for k_final.
__global__ __launch_bounds__(256, 5) void k_stats(const float4* __restrict__ x4) {
    constexpr int PAIRS = NPTS / 2;
    int warp = threadIdx.x >> 5, lane = threadIdx.x & 31;
    int j = lane & 15, seg = lane >> 4;
    unsigned offl = (unsigned)((seg << 5) + j);           // seg*32 + j
    float e0 = (j == 0) ? 1.f : 0.f;
    float4 mA = g_mean4[j], mB = g_mean4[j + 16];
    float m0 = ((const float*)g_mean4)[0];
    float inv1pm0 = 1.f / (1.f + m0);
    float mAxs = (j == 0) ? -mA.x : mA.x;

    float4 ssA = make_float4(0,0,0,0), ssB = make_float4(0,0,0,0);
    float4 sqA = make_float4(0,0,0,0), sqB = make_float4(0,0,0,0);
    int gw = blockIdx.x * 8 + warp;

    for (int pp = PAIRS - 1 - gw; pp >= 0; pp -= NW_STATS) {   // reverse sweep
        // depth-2 L2 prefetch (register-free); clamp keeps address valid
        {
            int pf = pp - 2 * NW_STATS; if (pf < 0) pf = 0;
            pfL2(&x4[(unsigned)pf * 64u + offl]);
        }
        unsigned bi = (unsigned)pp * 64u + offl;
        float4 vA = x4[bi];
        float4 vB = x4[bi + 16u];
        float dp = vA.x*mAxs + vA.y*mA.y + vA.z*mA.z + vA.w*mA.w + dot4(vB, mB);
        dp = segsum(dp);
        float x0 = __shfl_sync(0xffffffffu, vA.x, lane & 16);  // segment base lane
        float alpha  = fmaxf(-dp, 1.0f + 1e-7f);
        float uu     = fmaf(alpha, alpha, -1.0f);
        float runorm = rsqrtf(uu);
        float fac    = __logf(alpha + uu * runorm) * runorm;   // acosh(a)/|u|
        float u0     = fmaf(-alpha, m0, x0);
        float coef   = -fac * u0 * inv1pm0;                    // transp0back
        float c2     = fmaf(-fac, alpha, coef);
        if (j == 0)                                            // cache for k_final
            g_scal[(unsigned)pp * 2u + seg] = make_float4(fac, c2, coef, 0.f);
        float4 tA, tB;
        tA.x = fmaf(fac, vA.x, fmaf(c2, mA.x, coef * e0));
        tA.y = fmaf(fac, vA.y, c2 * mA.y);
        tA.z = fmaf(fac, vA.z, c2 * mA.z);
        tA.w = fmaf(fac, vA.w, c2 * mA.w);
        tB.x = fmaf(fac, vB.x, c2 * mB.x);
        tB.y = fmaf(fac, vB.y, c2 * mB.y);
        tB.z = fmaf(fac, vB.z, c2 * mB.z);
        tB.w = fmaf(fac, vB.w, c2 * mB.w);
        ssA.x += tA.x; ssA.y += tA.y; ssA.z += tA.z; ssA.w += tA.w;
        ssB.x += tB.x; ssB.y += tB.y; ssB.z += tB.z; ssB.w += tB.w;
        sqA.x = fmaf(tA.x, tA.x, sqA.x); sqA.y = fmaf(tA.y, tA.y, sqA.y);
        sqA.z = fmaf(tA.z, tA.z, sqA.z); sqA.w = fmaf(tA.w, tA.w, sqA.w);
        sqB.x = fmaf(tB.x, tB.x, sqB.x); sqB.y = fmaf(tB.y, tB.y, sqB.y);
        sqB.z = fmaf(tB.z, tB.z, sqB.z); sqB.w = fmaf(tB.w, tB.w, sqB.w);
    }

    // merge the two segments (same features): one xor-16 pass
    float acc[16] = {ssA.x,ssA.y,ssA.z,ssA.w, ssB.x,ssB.y,ssB.z,ssB.w,
                     sqA.x,sqA.y,sqA.z,sqA.w, sqB.x,sqB.y,sqB.z,sqB.w};
#pragma unroll
    for (int i = 0; i < 16; i++) acc[i] += __shfl_xor_sync(0xffffffffu, acc[i], 16);

    __shared__ float shs[8 * 128];
    __shared__ float shq[8 * 128];
    if (lane < 16) {
        int o = warp * 128 + j * 4;
#pragma unroll
        for (int c = 0; c < 4; c++) {
            shs[o + c]      = acc[c];
            shs[o + 64 + c] = acc[4 + c];
            shq[o + c]      = acc[8 + c];
            shq[o + 64 + c] = acc[12 + c];
        }
    }
    __syncthreads();
    if (threadIdx.x < 128) {
        float a = 0.f, b = 0.f;
#pragma unroll
        for (int w = 0; w < 8; w++) { a += shs[w*128 + threadIdx.x]; b += shq[w*128 + threadIdx.x]; }
        atomicAdd(&g_fs[threadIdx.x], (double)a);
        atomicAdd(&g_fq[threadIdx.x], (double)b);
    }
}

// per-feature scale = gamma / (sqrt(var + eps) + eps), for float4 group idx
__device__ __forceinline__ float4 load_scale(const float4* gamma4, int idx) {
    float4 g = gamma4[idx];
    float gv[4] = {g.x, g.y, g.z, g.w};
    float sv[4];
#pragma unroll
    for (int c = 0; c < 4; c++) {
        int d = idx * 4 + c;
        float mv  = (float)(g_fs[d] * (1.0 / NPTS));
        float var = (float)(g_fq[d] * (1.0 / NPTS)) - mv * mv;
        float std = sqrtf(fmaxf(var, 0.f) + 1e-5f);
        sv[c] = gv[c] / (std + 1e-5f);
    }
    return make_float4(sv[0], sv[1], sv[2], sv[3]);
}

// Pass 4: consume cached (fac, c2, coef): t = fac*x + c2*m + coef*o directly.
// Origin hot path: depth-1 register prefetch + depth-2 L2 prefetch hints.
__global__ __launch_bounds__(256) void k_final(const float4* __restrict__ x4,
                                               const float4* __restrict__ gamma4,
                                               const float4* __restrict__ beta4,
                                               float4* __restrict__ out4) {
    constexpr int PAIRS = NPTS / 2;
    int warp = threadIdx.x >> 5, lane = threadIdx.x & 31;
    int j = lane & 15, seg = lane >> 4;
    unsigned offl = (unsigned)((seg << 5) + j);
    float e0 = (j == 0) ? 1.f : 0.f;
    float4 mA = g_mean4[j], mB = g_mean4[j + 16];
    float4 sclA = load_scale(gamma4, j);
    float4 sclB = load_scale(gamma4, j + 16);

    // uniform beta-origin check (beta regs die after this in the hot path)
    bool is_origin;
    {
        float4 beA0 = beta4[j], beB0 = beta4[j + 16];
        float b00 = __shfl_sync(0xffffffffu, beA0.x, lane & 16);
        float bsq = segsum(dot4(beA0, beA0) + dot4(beB0, beB0));
        is_origin = (b00 == 1.0f) && (bsq - b00 * b00 <= 0.0f);
    }

    int gw = blockIdx.x * 8 + warp;

    if (is_origin) {
        // ---- hot path: transp0 = identity; depth-1 reg + depth-2 L2 prefetch ----
        int pp = gw;
        float4 vA, vB, sc;
        if (pp < PAIRS) {
            unsigned bi = (unsigned)pp * 64u + offl;
            vA = __ldcs(&x4[bi]);
            vB = __ldcs(&x4[bi + 16u]);
            sc = __ldg(&g_scal[(unsigned)pp * 2u + seg]);
        }
        while (pp < PAIRS) {
            int pn = pp + NW_FIN;
            {   // depth-2 L2 prefetch hint (register-free; clamped)
                int pf = pp + 2 * NW_FIN; if (pf >= PAIRS) pf = PAIRS - 1;
                pfL2(&x4[(unsigned)pf * 64u + offl]);
            }
            float4 vAn, vBn, scn;
            if (pn < PAIRS) {
                unsigned bni = (unsigned)pn * 64u + offl;
                vAn = __ldcs(&x4[bni]);
                vBn = __ldcs(&x4[bni + 16u]);
                scn = __ldg(&g_scal[(unsigned)pn * 2u + seg]);
            }
            float fac = sc.x, c2 = sc.y, coef = sc.z;
            float4 tA, tB;
            tA.x = sclA.x * fmaf(fac, vA.x, fmaf(c2, mA.x, coef * e0));
            tA.y = sclA.y * fmaf(fac, vA.y, c2 * mA.y);
            tA.z = sclA.z * fmaf(fac, vA.z, c2 * mA.z);
            tA.w = sclA.w * fmaf(fac, vA.w, c2 * mA.w);
            tB.x = sclB.x * fmaf(fac, vB.x, c2 * mB.x);
            tB.y = sclB.y * fmaf(fac, vB.y, c2 * mB.y);
            tB.z = sclB.z * fmaf(fac, vB.z, c2 * mB.z);
            tB.w = sclB.w * fmaf(fac, vB.w, c2 * mB.w);
            float re = dot4(tA, tA) + dot4(tB, tB);
            re = segsum(re);
            float rre = fmaxf(re, 1e-8f);
            float rq  = rsqrtf(rre);
            float en  = rre * rq;                    // ||t||
            float nu  = fminf(en, 32.f);             // esc * ||t||
            float ex  = __expf(nu);
            float exi = __expf(-nu);
            float ch  = 0.5f * (ex + exi);
            float sf  = 0.5f * (ex - exi) / en;      // esc * sinh(nu)/nu
            float4 oA, oB;
            oA.x = fmaf(sf, tA.x, ch * e0);
            oA.y = sf * tA.y; oA.z = sf * tA.z; oA.w = sf * tA.w;
            oB.x = sf * tB.x; oB.y = sf * tB.y; oB.z = sf * tB.z; oB.w = sf * tB.w;
            unsigned bo = (unsigned)pp * 64u + offl;
            __stcs(&out4[bo], oA);
            __stcs(&out4[bo + 16u], oB);
            vA = vAn; vB = vBn; sc = scn;
            pp = pn;
        }
    } else {
        // ---- general fallback: arbitrary beta on the hyperboloid ----
        float4 beA = beta4[j], beB = beta4[j + 16];
        float b0 = __shfl_sync(0xffffffffu, beA.x, lane & 16);
        float inv1pb0 = 1.f / (1.f + b0);
        float beAxs = (j == 0) ? -beA.x : beA.x;
        for (int pp = gw; pp < PAIRS; pp += NW_FIN) {
            unsigned bi = (unsigned)pp * 64u + offl;
            float4 vA = __ldcs(&x4[bi]);
            float4 vB = __ldcs(&x4[bi + 16u]);
            float4 sc = __ldg(&g_scal[(unsigned)pp * 2u + seg]);
            float fac = sc.x, c2 = sc.y, coef = sc.z;
            float4 tA, tB;
            tA.x = sclA.x * fmaf(fac, vA.x, fmaf(c2, mA.x, coef * e0));
            tA.y = sclA.y * fmaf(fac, vA.y, c2 * mA.y);
            tA.z = sclA.z * fmaf(fac, vA.z, c2 * mA.z);
            tA.w = sclA.w * fmaf(fac, vA.w, c2 * mA.w);
            tB.x = sclB.x * fmaf(fac, vB.x, c2 * mB.x);
            tB.y = sclB.y * fmaf(fac, vB.y, c2 * mB.y);
            tB.z = sclB.z * fmaf(fac, vB.z, c2 * mB.z);
            tB.w = sclB.w * fmaf(fac, vB.w, c2 * mB.w);
            float re = dot4(tA, tA) + dot4(tB, tB);
            float rb = tA.x*beAxs + tA.y*beA.y + tA.z*beA.z + tA.w*beA.w + dot4(tB, beB);
            segsum2(re, rb);
            float rre = fmaxf(re, 1e-8f);
            float rq  = rsqrtf(rre);
            float esc = fminf(1.f, 32.f * rq);       // euclid cap
            float coefb = esc * rb * inv1pb0;        // transp0(beta)
            float4 wA, wB;
            wA.x = fmaf(coefb, beA.x + e0, esc * tA.x);
            wA.y = fmaf(coefb, beA.y, esc * tA.y);
            wA.z = fmaf(coefb, beA.z, esc * tA.z);
            wA.w = fmaf(coefb, beA.w, esc * tA.w);
            wB.x = fmaf(coefb, beB.x, esc * tB.x);
            wB.y = fmaf(coefb, beB.y, esc * tB.y);
            wB.z = fmaf(coefb, beB.z, esc * tB.z);
            wB.w = fmaf(coefb, beB.w, esc * tB.w);
            float nu  = fminf(rre * rq, 32.f);       // linner(w,w)=esc^2*re
            float rnu = fmaxf(nu, 1e-4f);
            float ex  = __expf(rnu);
            float exi = __expf(-rnu);
            float ch  = 0.5f * (ex + exi);
            float shn = 0.5f * (ex - exi) / rnu;
            float4 oA, oB;
            oA.x = fmaf(ch, beA.x, shn * wA.x);
            oA.y = fmaf(ch, beA.y, shn * wA.y);
            oA.z = fmaf(ch, beA.z, shn * wA.z);
            oA.w = fmaf(ch, beA.w, shn * wA.w);
            oB.x = fmaf(ch, beB.x, shn * wB.x);
            oB.y = fmaf(ch, beB.y, shn * wB.y);
            oB.z = fmaf(ch, beB.z, shn * wB.z);
            oB.w = fmaf(ch, beB.w, shn * wB.w);
            __stcs(&out4[bi], oA);
            __stcs(&out4[bi + 16u], oB);
        }
    }
}

extern "C" void kernel_launch(void* const* d_in, const int* in_sizes, int n_in,
                              void* d_out, int out_size) {
    const float4* x  = (const float4*)d_in[0];
    const float4* ga = (const float4*)d_in[1];
    const float4* be = (const float4*)d_in[2];
    float4* out = (float4*)d_out;
    (void)in_sizes; (void)n_in; (void)out_size;

    k_sumS<<<BB * CHUNKS, 256>>>(x);
    k_centroid<<<1, 1024>>>();
    k_stats<<<GRID_STATS, 256>>>(x);
    k_final<<<GRID_FIN, 256>>>(x, ga, be, out);
}

// round 14
// speedup vs baseline: 1.4046x; 1.4046x over previous
#include <cuda_runtime.h>

#define BB 64
#define SS 4096
#define DD 128
#define NPTS (BB*SS)
#define CHUNKS 16
#define PPB (SS/CHUNKS)
#define GRID_STATS 740            // 5 blocks/SM * 148 SMs, one wave
#define NW_STATS (GRID_STATS * 8)
#define GRID_FO 740               // 5 blocks/SM * 148 SMs, one wave
#define NW_FO (GRID_FO * 8)
#define GRID_FG 592               // 4 blocks/SM, general fallback
#define NW_FG (GRID_FG * 8)

// scratch (allocation-free rule: __device__ globals)
__device__ float  g_part[CHUNKS*BB*DD]; // per-(chunk,b,d) partial sums
__device__ float4 g_mean4[DD/4];        // global Lorentz centroid
__device__ double g_fs[DD];             // per-feature sum of x_T
__device__ double g_fq[DD];             // per-feature sum of x_T^2
__device__ float4 g_scal[NPTS];         // per-point (fac, c2, coef) from k_stats
__device__ int    g_is_origin;          // beta == (1,0,...,0)? (set by k_centroid)

__device__ __forceinline__ float wsum(float v) {
#pragma unroll
    for (int o = 16; o; o >>= 1) v += __shfl_xor_sync(0xffffffffu, v, o);
    return v;
}

// 16-lane-segment reduction: 4 stages, reduces two points per warp at once
__device__ __forceinline__ float segsum(float v) {
#pragma unroll
    for (int o = 8; o; o >>= 1) v += __shfl_xor_sync(0xffffffffu, v, o);
    return v;
}
__device__ __forceinline__ void segsum2(float& a, float& b) {
#pragma unroll
    for (int o = 8; o; o >>= 1) {
        float ta = __shfl_xor_sync(0xffffffffu, a, o);
        float tb = __shfl_xor_sync(0xffffffffu, b, o);
        a += ta; b += tb;
    }
}
__device__ __forceinline__ float dot4(float4 a, float4 b) {
    return a.x*b.x + a.y*b.y + a.z*b.z + a.w*b.w;
}

// Pass 1: per-(b,chunk) sums over 256 points -> g_part (no atomics, no init)
__global__ __launch_bounds__(256) void k_sumS(const float4* __restrict__ x4) {
    int b     = blockIdx.x >> 4;
    int chunk = blockIdx.x & 15;
    int warp = threadIdx.x >> 5, lane = threadIdx.x & 31;
    const float4* base = x4 + ((size_t)b * SS + (size_t)chunk * PPB) * 32 + lane;
    float4 acc = make_float4(0.f, 0.f, 0.f, 0.f);
#pragma unroll 4
    for (int s = warp; s < PPB; s += 8) {
        float4 v = base[(size_t)s * 32];
        acc.x += v.x; acc.y += v.y; acc.z += v.z; acc.w += v.w;
    }
    __shared__ float sh[8 * 128];
    int o = warp * 128 + lane * 4;
    sh[o] = acc.x; sh[o+1] = acc.y; sh[o+2] = acc.z; sh[o+3] = acc.w;
    __syncthreads();
    if (threadIdx.x < 128) {
        float v = 0.f;
#pragma unroll
        for (int w = 0; w < 8; w++) v += sh[w * 128 + threadIdx.x];
        g_part[(chunk * BB + b) * DD + threadIdx.x] = v;
    }
}

// Pass 2 (tiny): reduce partials, centroid of centroids, zero stats, beta flag
__global__ __launch_bounds__(1024) void k_centroid(const float4* __restrict__ beta4) {
    __shared__ float sh1[BB * DD];
    __shared__ float red[128];
    __shared__ float s_linner;
    int tid = threadIdx.x, warp = tid >> 5, lane = tid & 31;

    for (int idx = tid; idx < BB*DD; idx += 1024) {
        float s = 0.f;
#pragma unroll
        for (int c = 0; c < CHUNKS; c++) s += g_part[c * BB * DD + idx];
        sh1[idx] = s;
    }
    if (tid < DD) { g_fs[tid] = 0.0; g_fq[tid] = 0.0; }

    // beta-origin flag (warp 31; doesn't touch sh1)
    if (warp == 31) {
        float4 be = beta4[lane];
        float b0  = __shfl_sync(0xffffffffu, be.x, 0);
        float bsq = wsum(be.x*be.x + be.y*be.y + be.z*be.z + be.w*be.w);
        if (lane == 0) g_is_origin = ((b0 == 1.0f) && (bsq - b0 * b0 <= 0.0f)) ? 1 : 0;
    }
    __syncthreads();

#pragma unroll
    for (int rep = 0; rep < 2; rep++) {
        int b = warp + rep * 32;
        float a[4];
        float lc = 0.f;
#pragma unroll
        for (int j = 0; j < 4; j++) {
            a[j] = sh1[b * 128 + lane * 4 + j] * (1.f / SS);
            float c = a[j] * a[j];
            if (lane == 0 && j == 0) c = -c;
            lc += c;
        }
        lc = wsum(lc);
        float denom = sqrtf(fmaxf(-lc, 1e-8f));
#pragma unroll
        for (int j = 0; j < 4; j++) sh1[b * 128 + lane * 4 + j] = a[j] / denom;
    }
    __syncthreads();

    float a2 = 0.f;
    if (tid < 128) {
        float s = 0.f;
        for (int b = 0; b < BB; b++) s += sh1[b * 128 + tid];
        a2 = s * (1.f / BB);
        float c = a2 * a2;
        red[tid] = (tid == 0) ? -c : c;
    }
    __syncthreads();
    for (int off = 64; off > 0; off >>= 1) {
        if (tid < off) red[tid] += red[tid + off];
        __syncthreads();
    }
    if (tid == 0) s_linner = red[0];
    __syncthreads();
    if (tid < 128) {
        float denom2 = sqrtf(fmaxf(-s_linner, 1e-8f));
        ((float*)g_mean4)[tid] = a2 / denom2;
    }
}

// Pass 3: per-feature sum / sumsq of x_T. 16-lane segments: each half-warp
// owns one point (8 features/lane as 2 float4), 2 points per warp-iteration.
// ALSO caches (fac, c2, coef) per point for k_final.
__global__ __launch_bounds__(256, 5) void k_stats(const float4* __restrict__ x4) {
    constexpr int PAIRS = NPTS / 2;
    int warp = threadIdx.x >> 5, lane = threadIdx.x & 31;
    int j = lane & 15, seg = lane >> 4;
    unsigned offl = (unsigned)((seg << 5) + j);           // seg*32 + j
    float e0 = (j == 0) ? 1.f : 0.f;
    float4 mA = g_mean4[j], mB = g_mean4[j + 16];
    float m0 = ((const float*)g_mean4)[0];
    float inv1pm0 = 1.f / (1.f + m0);
    float mAxs = (j == 0) ? -mA.x : mA.x;

    float4 ssA = make_float4(0,0,0,0), ssB = make_float4(0,0,0,0);
    float4 sqA = make_float4(0,0,0,0), sqB = make_float4(0,0,0,0);
    int gw = blockIdx.x * 8 + warp;

    for (int pp = PAIRS - 1 - gw; pp >= 0; pp -= NW_STATS) {   // reverse sweep
        unsigned bi = (unsigned)pp * 64u + offl;
        float4 vA = x4[bi];
        float4 vB = x4[bi + 16u];
        float dp = vA.x*mAxs + vA.y*mA.y + vA.z*mA.z + vA.w*mA.w + dot4(vB, mB);
        dp = segsum(dp);
        float x0 = __shfl_sync(0xffffffffu, vA.x, lane & 16);  // segment base lane
        float alpha  = fmaxf(-dp, 1.0f + 1e-7f);
        float uu     = fmaf(alpha, alpha, -1.0f);
        float runorm = rsqrtf(uu);
        float fac    = __logf(alpha + uu * runorm) * runorm;   // acosh(a)/|u|
        float u0     = fmaf(-alpha, m0, x0);
        float coef   = -fac * u0 * inv1pm0;                    // transp0back
        float c2     = fmaf(-fac, alpha, coef);
        if (j == 0)                                            // cache for k_final
            g_scal[(unsigned)pp * 2u + seg] = make_float4(fac, c2, coef, 0.f);
        float4 tA, tB;
        tA.x = fmaf(fac, vA.x, fmaf(c2, mA.x, coef * e0));
        tA.y = fmaf(fac, vA.y, c2 * mA.y);
        tA.z = fmaf(fac, vA.z, c2 * mA.z);
        tA.w = fmaf(fac, vA.w, c2 * mA.w);
        tB.x = fmaf(fac, vB.x, c2 * mB.x);
        tB.y = fmaf(fac, vB.y, c2 * mB.y);
        tB.z = fmaf(fac, vB.z, c2 * mB.z);
        tB.w = fmaf(fac, vB.w, c2 * mB.w);
        ssA.x += tA.x; ssA.y += tA.y; ssA.z += tA.z; ssA.w += tA.w;
        ssB.x += tB.x; ssB.y += tB.y; ssB.z += tB.z; ssB.w += tB.w;
        sqA.x = fmaf(tA.x, tA.x, sqA.x); sqA.y = fmaf(tA.y, tA.y, sqA.y);
        sqA.z = fmaf(tA.z, tA.z, sqA.z); sqA.w = fmaf(tA.w, tA.w, sqA.w);
        sqB.x = fmaf(tB.x, tB.x, sqB.x); sqB.y = fmaf(tB.y, tB.y, sqB.y);
        sqB.z = fmaf(tB.z, tB.z, sqB.z); sqB.w = fmaf(tB.w, tB.w, sqB.w);
    }

    // merge the two segments (same features): one xor-16 pass
    float acc[16] = {ssA.x,ssA.y,ssA.z,ssA.w, ssB.x,ssB.y,ssB.z,ssB.w,
                     sqA.x,sqA.y,sqA.z,sqA.w, sqB.x,sqB.y,sqB.z,sqB.w};
#pragma unroll
    for (int i = 0; i < 16; i++) acc[i] += __shfl_xor_sync(0xffffffffu, acc[i], 16);

    __shared__ float shs[8 * 128];
    __shared__ float shq[8 * 128];
    if (lane < 16) {
        int o = warp * 128 + j * 4;
#pragma unroll
        for (int c = 0; c < 4; c++) {
            shs[o + c]      = acc[c];
            shs[o + 64 + c] = acc[4 + c];
            shq[o + c]      = acc[8 + c];
            shq[o + 64 + c] = acc[12 + c];
        }
    }
    __syncthreads();
    if (threadIdx.x < 128) {
        float a = 0.f, b = 0.f;
#pragma unroll
        for (int w = 0; w < 8; w++) { a += shs[w*128 + threadIdx.x]; b += shq[w*128 + threadIdx.x]; }
        atomicAdd(&g_fs[threadIdx.x], (double)a);
        atomicAdd(&g_fq[threadIdx.x], (double)b);
    }
}

// per-feature scale = gamma / (sqrt(var + eps) + eps), for float4 group idx
__device__ __forceinline__ float4 load_scale(const float4* gamma4, int idx) {
    float4 g = gamma4[idx];
    float gv[4] = {g.x, g.y, g.z, g.w};
    float sv[4];
#pragma unroll
    for (int c = 0; c < 4; c++) {
        int d = idx * 4 + c;
        float mv  = (float)(g_fs[d] * (1.0 / NPTS));
        float var = (float)(g_fq[d] * (1.0 / NPTS)) - mv * mv;
        float std = sqrtf(fmaxf(var, 0.f) + 1e-5f);
        sv[c] = gv[c] / (std + 1e-5f);
    }
    return make_float4(sv[0], sv[1], sv[2], sv[3]);
}

// Pass 4 (hot): beta == origin (flag). No beta registers; depth-1 prefetch.
// t = fac*x + c2*m + coef*o from cached scalars; transp0 = identity.
__global__ __launch_bounds__(256, 5) void k_final_o(const float4* __restrict__ x4,
                                                    const float4* __restrict__ gamma4,
                                                    float4* __restrict__ out4) {
    if (!g_is_origin) return;                     // fallback kernel handles it
    constexpr int PAIRS = NPTS / 2;
    int warp = threadIdx.x >> 5, lane = threadIdx.x & 31;
    int j = lane & 15, seg = lane >> 4;
    unsigned offl = (unsigned)((seg << 5) + j);
    float e0 = (j == 0) ? 1.f : 0.f;
    float4 mA = g_mean4[j], mB = g_mean4[j + 16];
    float4 sclA = load_scale(gamma4, j);
    float4 sclB = load_scale(gamma4, j + 16);

    int gw = blockIdx.x * 8 + warp;
    int pp = gw;
    float4 vA, vB, sc;
    if (pp < PAIRS) {
        unsigned bi = (unsigned)pp * 64u + offl;
        vA = __ldcs(&x4[bi]);
        vB = __ldcs(&x4[bi + 16u]);
        sc = __ldg(&g_scal[(unsigned)pp * 2u + seg]);
    }
    while (pp < PAIRS) {
        int pn = pp + NW_FO;
        float4 vAn, vBn, scn;
        if (pn < PAIRS) {
            unsigned bni = (unsigned)pn * 64u + offl;
            vAn = __ldcs(&x4[bni]);
            vBn = __ldcs(&x4[bni + 16u]);
            scn = __ldg(&g_scal[(unsigned)pn * 2u + seg]);
        }
        float fac = sc.x, c2 = sc.y, coef = sc.z;
        float4 tA, tB;
        tA.x = sclA.x * fmaf(fac, vA.x, fmaf(c2, mA.x, coef * e0));
        tA.y = sclA.y * fmaf(fac, vA.y, c2 * mA.y);
        tA.z = sclA.z * fmaf(fac, vA.z, c2 * mA.z);
        tA.w = sclA.w * fmaf(fac, vA.w, c2 * mA.w);
        tB.x = sclB.x * fmaf(fac, vB.x, c2 * mB.x);
        tB.y = sclB.y * fmaf(fac, vB.y, c2 * mB.y);
        tB.z = sclB.z * fmaf(fac, vB.z, c2 * mB.z);
        tB.w = sclB.w * fmaf(fac, vB.w, c2 * mB.w);
        float re = dot4(tA, tA) + dot4(tB, tB);
        re = segsum(re);
        float rre = fmaxf(re, 1e-8f);
        float rq  = rsqrtf(rre);
        float en  = rre * rq;                    // ||t||
        float nu  = fminf(en, 32.f);             // esc * ||t||
        float ex  = __expf(nu);
        float exi = __expf(-nu);
        float ch  = 0.5f * (ex + exi);
        float sf  = 0.5f * (ex - exi) / en;      // esc * sinh(nu)/nu
        float4 oA, oB;
        oA.x = fmaf(sf, tA.x, ch * e0);
        oA.y = sf * tA.y; oA.z = sf * tA.z; oA.w = sf * tA.w;
        oB.x = sf * tB.x; oB.y = sf * tB.y; oB.z = sf * tB.z; oB.w = sf * tB.w;
        unsigned bo = (unsigned)pp * 64u + offl;
        __stcs(&out4[bo], oA);
        __stcs(&out4[bo + 16u], oB);
        vA = vAn; vB = vBn; sc = scn;
        pp = pn;
    }
}

// Pass 4 (general fallback): arbitrary beta on the hyperboloid. Flag-exits fast.
__global__ __launch_bounds__(256) void k_final_g(const float4* __restrict__ x4,
                                                 const float4* __restrict__ gamma4,
                                                 const float4* __restrict__ beta4,
                                                 float4* __restrict__ out4) {
    if (g_is_origin) return;                      // hot kernel handled it
    constexpr int PAIRS = NPTS / 2;
    int warp = threadIdx.x >> 5, lane = threadIdx.x & 31;
    int j = lane & 15, seg = lane >> 4;
    unsigned offl = (unsigned)((seg << 5) + j);
    float e0 = (j == 0) ? 1.f : 0.f;
    float4 mA = g_mean4[j], mB = g_mean4[j + 16];
    float4 sclA = load_scale(gamma4, j);
    float4 sclB = load_scale(gamma4, j + 16);
    float4 beA = beta4[j], beB = beta4[j + 16];
    float b0 = __shfl_sync(0xffffffffu, beA.x, lane & 16);
    float inv1pb0 = 1.f / (1.f + b0);
    float beAxs = (j == 0) ? -beA.x : beA.x;

    int gw = blockIdx.x * 8 + warp;
    for (int pp = gw; pp < PAIRS; pp += NW_FG) {
        unsigned bi = (unsigned)pp * 64u + offl;
        float4 vA = __ldcs(&x4[bi]);
        float4 vB = __ldcs(&x4[bi + 16u]);
        float4 sc = __ldg(&g_scal[(unsigned)pp * 2u + seg]);
        float fac = sc.x, c2 = sc.y, coef = sc.z;
        float4 tA, tB;
        tA.x = sclA.x * fmaf(fac, vA.x, fmaf(c2, mA.x, coef * e0));
        tA.y = sclA.y * fmaf(fac, vA.y, c2 * mA.y);
        tA.z = sclA.z * fmaf(fac, vA.z, c2 * mA.z);
        tA.w = sclA.w * fmaf(fac, vA.w, c2 * mA.w);
        tB.x = sclB.x * fmaf(fac, vB.x, c2 * mB.x);
        tB.y = sclB.y * fmaf(fac, vB.y, c2 * mB.y);
        tB.z = sclB.z * fmaf(fac, vB.z, c2 * mB.z);
        tB.w = sclB.w * fmaf(fac, vB.w, c2 * mB.w);
        float re = dot4(tA, tA) + dot4(tB, tB);
        float rb = tA.x*beAxs + tA.y*beA.y + tA.z*beA.z + tA.w*beA.w + dot4(tB, beB);
        segsum2(re, rb);
        float rre = fmaxf(re, 1e-8f);
        float rq  = rsqrtf(rre);
        float esc = fminf(1.f, 32.f * rq);       // euclid cap
        float coefb = esc * rb * inv1pb0;        // transp0(beta)
        float4 wA, wB;
        wA.x = fmaf(coefb, beA.x + e0, esc * tA.x);
        wA.y = fmaf(coefb, beA.y, esc * tA.y);
        wA.z = fmaf(coefb, beA.z, esc * tA.z);
        wA.w = fmaf(coefb, beA.w, esc * tA.w);
        wB.x = fmaf(coefb, beB.x, esc * tB.x);
        wB.y = fmaf(coefb, beB.y, esc * tB.y);
        wB.z = fmaf(coefb, beB.z, esc * tB.z);
        wB.w = fmaf(coefb, beB.w, esc * tB.w);
        float nu  = fminf(rre * rq, 32.f);       // linner(w,w)=esc^2*re
        float rnu = fmaxf(nu, 1e-4f);
        float ex  = __expf(rnu);
        float exi = __expf(-rnu);
        float ch  = 0.5f * (ex + exi);
        float shn = 0.5f * (ex - exi) / rnu;
        float4 oA, oB;
        oA.x = fmaf(ch, beA.x, shn * wA.x);
        oA.y = fmaf(ch, beA.y, shn * wA.y);
        oA.z = fmaf(ch, beA.z, shn * wA.z);
        oA.w = fmaf(ch, beA.w, shn * wA.w);
        oB.x = fmaf(ch, beB.x, shn * wB.x);
        oB.y = fmaf(ch, beB.y, shn * wB.y);
        oB.z = fmaf(ch, beB.z, shn * wB.z);
        oB.w = fmaf(ch, beB.w, shn * wB.w);
        __stcs(&out4[bi], oA);
        __stcs(&out4[bi + 16u], oB);
    }
}

extern "C" void kernel_launch(void* const* d_in, const int* in_sizes, int n_in,
                              void* d_out, int out_size) {
    const float4* x  = (const float4*)d_in[0];
    const float4* ga = (const float4*)d_in[1];
    const float4* be = (const float4*)d_in[2];
    float4* out = (float4*)d_out;
    (void)in_sizes; (void)n_in; (void)out_size;

    k_sumS<<<BB * CHUNKS, 256>>>(x);
    k_centroid<<<1, 1024>>>(be);
    k_stats<<<GRID_STATS, 256>>>(x);
    k_final_o<<<GRID_FO, 256>>>(x, ga, out);
    k_final_g<<<GRID_FG, 256>>>(x, ga, be, out);
}

// round 15
// speedup vs baseline: 1.5439x; 1.0992x over previous
#include <cuda_runtime.h>

#define BB 64
#define SS 4096
#define DD 128
#define NPTS (BB*SS)
#define CHUNKS 16
#define PPB (SS/CHUNKS)
#define GRID_STATS 592            // 4 blocks/SM * 148 SMs (prefetch needs regs)
#define NW_STATS (GRID_STATS * 8)
#define GRID_FIN 592              // 4 blocks/SM * 148 SMs, one wave
#define NW_FIN (GRID_FIN * 8)

// scratch (allocation-free rule: __device__ globals)
__device__ float  g_part[CHUNKS*BB*DD]; // per-(chunk,b,d) partial sums
__device__ float4 g_mean4[DD/4];        // global Lorentz centroid
__device__ double g_fs[DD];             // per-feature sum of x_T
__device__ double g_fq[DD];             // per-feature sum of x_T^2
__device__ float4 g_scal[NPTS];         // per-point (fac, c2, coef) from k_stats

__device__ __forceinline__ float wsum(float v) {
#pragma unroll
    for (int o = 16; o; o >>= 1) v += __shfl_xor_sync(0xffffffffu, v, o);
    return v;
}

// 16-lane-segment reduction: 4 stages, reduces two points per warp at once
__device__ __forceinline__ float segsum(float v) {
#pragma unroll
    for (int o = 8; o; o >>= 1) v += __shfl_xor_sync(0xffffffffu, v, o);
    return v;
}
__device__ __forceinline__ void segsum2(float& a, float& b) {
#pragma unroll
    for (int o = 8; o; o >>= 1) {
        float ta = __shfl_xor_sync(0xffffffffu, a, o);
        float tb = __shfl_xor_sync(0xffffffffu, b, o);
        a += ta; b += tb;
    }
}
__device__ __forceinline__ float dot4(float4 a, float4 b) {
    return a.x*b.x + a.y*b.y + a.z*b.z + a.w*b.w;
}

// Pass 1: per-(b,chunk) sums over 256 points -> g_part (no atomics, no init)
__global__ __launch_bounds__(256) void k_sumS(const float4* __restrict__ x4) {
    int b     = blockIdx.x >> 4;
    int chunk = blockIdx.x & 15;
    int warp = threadIdx.x >> 5, lane = threadIdx.x & 31;
    const float4* base = x4 + ((size_t)b * SS + (size_t)chunk * PPB) * 32 + lane;
    float4 acc = make_float4(0.f, 0.f, 0.f, 0.f);
#pragma unroll 4
    for (int s = warp; s < PPB; s += 8) {
        float4 v = base[(size_t)s * 32];
        acc.x += v.x; acc.y += v.y; acc.z += v.z; acc.w += v.w;
    }
    __shared__ float sh[8 * 128];
    int o = warp * 128 + lane * 4;
    sh[o] = acc.x; sh[o+1] = acc.y; sh[o+2] = acc.z; sh[o+3] = acc.w;
    __syncthreads();
    if (threadIdx.x < 128) {
        float v = 0.f;
#pragma unroll
        for (int w = 0; w < 8; w++) v += sh[w * 128 + threadIdx.x];
        g_part[(chunk * BB + b) * DD + threadIdx.x] = v;
    }
}

// Pass 2 (tiny): reduce partials, centroid of per-batch centroids, zero stats
__global__ __launch_bounds__(1024) void k_centroid() {
    __shared__ float sh1[BB * DD];
    __shared__ float red[128];
    __shared__ float s_linner;
    int tid = threadIdx.x, warp = tid >> 5, lane = tid & 31;

    for (int idx = tid; idx < BB*DD; idx += 1024) {
        float s = 0.f;
#pragma unroll
        for (int c = 0; c < CHUNKS; c++) s += g_part[c * BB * DD + idx];
        sh1[idx] = s;
    }
    if (tid < DD) { g_fs[tid] = 0.0; g_fq[tid] = 0.0; }
    __syncthreads();

#pragma unroll
    for (int rep = 0; rep < 2; rep++) {
        int b = warp + rep * 32;
        float a[4];
        float lc = 0.f;
#pragma unroll
        for (int j = 0; j < 4; j++) {
            a[j] = sh1[b * 128 + lane * 4 + j] * (1.f / SS);
            float c = a[j] * a[j];
            if (lane == 0 && j == 0) c = -c;
            lc += c;
        }
        lc = wsum(lc);
        float denom = sqrtf(fmaxf(-lc, 1e-8f));
#pragma unroll
        for (int j = 0; j < 4; j++) sh1[b * 128 + lane * 4 + j] = a[j] / denom;
    }
    __syncthreads();

    float a2 = 0.f;
    if (tid < 128) {
        float s = 0.f;
        for (int b = 0; b < BB; b++) s += sh1[b * 128 + tid];
        a2 = s * (1.f / BB);
        float c = a2 * a2;
        red[tid] = (tid == 0) ? -c : c;
    }
    __syncthreads();
    for (int off = 64; off > 0; off >>= 1) {
        if (tid < off) red[tid] += red[tid + off];
        __syncthreads();
    }
    if (tid == 0) s_linner = red[0];
    __syncthreads();
    if (tid < 128) {
        float denom2 = sqrtf(fmaxf(-s_linner, 1e-8f));
        ((float*)g_mean4)[tid] = a2 / denom2;
    }
}

// Pass 3: per-feature sum / sumsq of x_T. 16-lane segments, reverse sweep,
// depth-1 register prefetch. Caches (fac, c2, coef) per point for k_final.
__global__ __launch_bounds__(256) void k_stats(const float4* __restrict__ x4) {
    constexpr int PAIRS = NPTS / 2;
    int warp = threadIdx.x >> 5, lane = threadIdx.x & 31;
    int j = lane & 15, seg = lane >> 4;
    unsigned offl = (unsigned)((seg << 5) + j);           // seg*32 + j
    float e0 = (j == 0) ? 1.f : 0.f;
    float4 mA = g_mean4[j], mB = g_mean4[j + 16];
    float m0 = ((const float*)g_mean4)[0];
    float inv1pm0 = 1.f / (1.f + m0);
    float mAxs = (j == 0) ? -mA.x : mA.x;

    float4 ssA = make_float4(0,0,0,0), ssB = make_float4(0,0,0,0);
    float4 sqA = make_float4(0,0,0,0), sqB = make_float4(0,0,0,0);
    int gw = blockIdx.x * 8 + warp;

    int pp = PAIRS - 1 - gw;                              // reverse sweep
    float4 vA, vB;
    if (pp >= 0) {
        unsigned bi = (unsigned)pp * 64u + offl;
        vA = x4[bi];
        vB = x4[bi + 16u];
    }
    while (pp >= 0) {
        int pn = pp - NW_STATS;
        float4 vAn, vBn;
        if (pn >= 0) {
            unsigned bni = (unsigned)pn * 64u + offl;
            vAn = x4[bni];
            vBn = x4[bni + 16u];
        }
        float dp = vA.x*mAxs + vA.y*mA.y + vA.z*mA.z + vA.w*mA.w + dot4(vB, mB);
        dp = segsum(dp);
        float x0 = __shfl_sync(0xffffffffu, vA.x, lane & 16);  // segment base lane
        float alpha  = fmaxf(-dp, 1.0f + 1e-7f);
        float uu     = fmaf(alpha, alpha, -1.0f);
        float runorm = rsqrtf(uu);
        float fac    = __logf(alpha + uu * runorm) * runorm;   // acosh(a)/|u|
        float u0     = fmaf(-alpha, m0, x0);
        float coef   = -fac * u0 * inv1pm0;                    // transp0back
        float c2     = fmaf(-fac, alpha, coef);
        if (j == 0)                                            // cache for k_final
            g_scal[(unsigned)pp * 2u + seg] = make_float4(fac, c2, coef, 0.f);
        float4 tA, tB;
        tA.x = fmaf(fac, vA.x, fmaf(c2, mA.x, coef * e0));
        tA.y = fmaf(fac, vA.y, c2 * mA.y);
        tA.z = fmaf(fac, vA.z, c2 * mA.z);
        tA.w = fmaf(fac, vA.w, c2 * mA.w);
        tB.x = fmaf(fac, vB.x, c2 * mB.x);
        tB.y = fmaf(fac, vB.y, c2 * mB.y);
        tB.z = fmaf(fac, vB.z, c2 * mB.z);
        tB.w = fmaf(fac, vB.w, c2 * mB.w);
        ssA.x += tA.x; ssA.y += tA.y; ssA.z += tA.z; ssA.w += tA.w;
        ssB.x += tB.x; ssB.y += tB.y; ssB.z += tB.z; ssB.w += tB.w;
        sqA.x = fmaf(tA.x, tA.x, sqA.x); sqA.y = fmaf(tA.y, tA.y, sqA.y);
        sqA.z = fmaf(tA.z, tA.z, sqA.z); sqA.w = fmaf(tA.w, tA.w, sqA.w);
        sqB.x = fmaf(tB.x, tB.x, sqB.x); sqB.y = fmaf(tB.y, tB.y, sqB.y);
        sqB.z = fmaf(tB.z, tB.z, sqB.z); sqB.w = fmaf(tB.w, tB.w, sqB.w);
        vA = vAn; vB = vBn;
        pp = pn;
    }

    // merge the two segments (same features): one xor-16 pass
    float acc[16] = {ssA.x,ssA.y,ssA.z,ssA.w, ssB.x,ssB.y,ssB.z,ssB.w,
                     sqA.x,sqA.y,sqA.z,sqA.w, sqB.x,sqB.y,sqB.z,sqB.w};
#pragma unroll
    for (int i = 0; i < 16; i++) acc[i] += __shfl_xor_sync(0xffffffffu, acc[i], 16);

    __shared__ float shs[8 * 128];
    __shared__ float shq[8 * 128];
    if (lane < 16) {
        int o = warp * 128 + j * 4;
#pragma unroll
        for (int c = 0; c < 4; c++) {
            shs[o + c]      = acc[c];
            shs[o + 64 + c] = acc[4 + c];
            shq[o + c]      = acc[8 + c];
            shq[o + 64 + c] = acc[12 + c];
        }
    }
    __syncthreads();
    if (threadIdx.x < 128) {
        float a = 0.f, b = 0.f;
#pragma unroll
        for (int w = 0; w < 8; w++) { a += shs[w*128 + threadIdx.x]; b += shq[w*128 + threadIdx.x]; }
        atomicAdd(&g_fs[threadIdx.x], (double)a);
        atomicAdd(&g_fq[threadIdx.x], (double)b);
    }
}

// per-feature scale = gamma / (sqrt(var + eps) + eps), for float4 group idx
__device__ __forceinline__ float4 load_scale(const float4* gamma4, int idx) {
    float4 g = gamma4[idx];
    float gv[4] = {g.x, g.y, g.z, g.w};
    float sv[4];
#pragma unroll
    for (int c = 0; c < 4; c++) {
        int d = idx * 4 + c;
        float mv  = (float)(g_fs[d] * (1.0 / NPTS));
        float var = (float)(g_fq[d] * (1.0 / NPTS)) - mv * mv;
        float std = sqrtf(fmaxf(var, 0.f) + 1e-5f);
        sv[c] = gv[c] / (std + 1e-5f);
    }
    return make_float4(sv[0], sv[1], sv[2], sv[3]);
}

// Pass 4: consume cached (fac, c2, coef): t = fac*x + c2*m + coef*o directly.
// Two disjoint loops chosen once (uniform): origin hot path (beta regs dead,
// depth-1 prefetch) vs general fallback.
__global__ __launch_bounds__(256) void k_final(const float4* __restrict__ x4,
                                               const float4* __restrict__ gamma4,
                                               const float4* __restrict__ beta4,
                                               float4* __restrict__ out4) {
    constexpr int PAIRS = NPTS / 2;
    int warp = threadIdx.x >> 5, lane = threadIdx.x & 31;
    int j = lane & 15, seg = lane >> 4;
    unsigned offl = (unsigned)((seg << 5) + j);
    float e0 = (j == 0) ? 1.f : 0.f;
    float4 mA = g_mean4[j], mB = g_mean4[j + 16];
    float4 sclA = load_scale(gamma4, j);
    float4 sclB = load_scale(gamma4, j + 16);

    // uniform beta-origin check (beta regs die after this in the hot path)
    bool is_origin;
    {
        float4 beA0 = beta4[j], beB0 = beta4[j + 16];
        float b00 = __shfl_sync(0xffffffffu, beA0.x, lane & 16);
        float bsq = segsum(dot4(beA0, beA0) + dot4(beB0, beB0));
        is_origin = (b00 == 1.0f) && (bsq - b00 * b00 <= 0.0f);
    }

    int gw = blockIdx.x * 8 + warp;

    if (is_origin) {
        // ---- hot path: transp0 = identity; depth-1 software prefetch ----
        int pp = gw;
        float4 vA, vB, sc;
        if (pp < PAIRS) {
            unsigned bi = (unsigned)pp * 64u + offl;
            vA = __ldcs(&x4[bi]);
            vB = __ldcs(&x4[bi + 16u]);
            sc = __ldg(&g_scal[(unsigned)pp * 2u + seg]);
        }
        while (pp < PAIRS) {
            int pn = pp + NW_FIN;
            float4 vAn, vBn, scn;
            if (pn < PAIRS) {
                unsigned bni = (unsigned)pn * 64u + offl;
                vAn = __ldcs(&x4[bni]);
                vBn = __ldcs(&x4[bni + 16u]);
                scn = __ldg(&g_scal[(unsigned)pn * 2u + seg]);
            }
            float fac = sc.x, c2 = sc.y, coef = sc.z;
            float4 tA, tB;
            tA.x = sclA.x * fmaf(fac, vA.x, fmaf(c2, mA.x, coef * e0));
            tA.y = sclA.y * fmaf(fac, vA.y, c2 * mA.y);
            tA.z = sclA.z * fmaf(fac, vA.z, c2 * mA.z);
            tA.w = sclA.w * fmaf(fac, vA.w, c2 * mA.w);
            tB.x = sclB.x * fmaf(fac, vB.x, c2 * mB.x);
            tB.y = sclB.y * fmaf(fac, vB.y, c2 * mB.y);
            tB.z = sclB.z * fmaf(fac, vB.z, c2 * mB.z);
            tB.w = sclB.w * fmaf(fac, vB.w, c2 * mB.w);
            float re = dot4(tA, tA) + dot4(tB, tB);
            re = segsum(re);
            float rre = fmaxf(re, 1e-8f);
            float rq  = rsqrtf(rre);
            float en  = rre * rq;                    // ||t||
            float nu  = fminf(en, 32.f);             // esc * ||t||
            float ex  = __expf(nu);
            float exi = __expf(-nu);
            float ch  = 0.5f * (ex + exi);
            float sf  = 0.5f * (ex - exi) / en;      // esc * sinh(nu)/nu
            float4 oA, oB;
            oA.x = fmaf(sf, tA.x, ch * e0);
            oA.y = sf * tA.y; oA.z = sf * tA.z; oA.w = sf * tA.w;
            oB.x = sf * tB.x; oB.y = sf * tB.y; oB.z = sf * tB.z; oB.w = sf * tB.w;
            unsigned bo = (unsigned)pp * 64u + offl;
            __stcs(&out4[bo], oA);
            __stcs(&out4[bo + 16u], oB);
            vA = vAn; vB = vBn; sc = scn;
            pp = pn;
        }
    } else {
        // ---- general fallback: arbitrary beta on the hyperboloid ----
        float4 beA = beta4[j], beB = beta4[j + 16];
        float b0 = __shfl_sync(0xffffffffu, beA.x, lane & 16);
        float inv1pb0 = 1.f / (1.f + b0);
        float beAxs = (j == 0) ? -beA.x : beA.x;
        for (int pp = gw; pp < PAIRS; pp += NW_FIN) {
            unsigned bi = (unsigned)pp * 64u + offl;
            float4 vA = __ldcs(&x4[bi]);
            float4 vB = __ldcs(&x4[bi + 16u]);
            float4 sc = __ldg(&g_scal[(unsigned)pp * 2u + seg]);
            float fac = sc.x, c2 = sc.y, coef = sc.z;
            float4 tA, tB;
            tA.x = sclA.x * fmaf(fac, vA.x, fmaf(c2, mA.x, coef * e0));
            tA.y = sclA.y * fmaf(fac, vA.y, c2 * mA.y);
            tA.z = sclA.z * fmaf(fac, vA.z, c2 * mA.z);
            tA.w = sclA.w * fmaf(fac, vA.w, c2 * mA.w);
            tB.x = sclB.x * fmaf(fac, vB.x, c2 * mB.x);
            tB.y = sclB.y * fmaf(fac, vB.y, c2 * mB.y);
            tB.z = sclB.z * fmaf(fac, vB.z, c2 * mB.z);
            tB.w = sclB.w * fmaf(fac, vB.w, c2 * mB.w);
            float re = dot4(tA, tA) + dot4(tB, tB);
            float rb = tA.x*beAxs + tA.y*beA.y + tA.z*beA.z + tA.w*beA.w + dot4(tB, beB);
            segsum2(re, rb);
            float rre = fmaxf(re, 1e-8f);
            float rq  = rsqrtf(rre);
            float esc = fminf(1.f, 32.f * rq);       // euclid cap
            float coefb = esc * rb * inv1pb0;        // transp0(beta)
            float4 wA, wB;
            wA.x = fmaf(coefb, beA.x + e0, esc * tA.x);
            wA.y = fmaf(coefb, beA.y, esc * tA.y);
            wA.z = fmaf(coefb, beA.z, esc * tA.z);
            wA.w = fmaf(coefb, beA.w, esc * tA.w);
            wB.x = fmaf(coefb, beB.x, esc * tB.x);
            wB.y = fmaf(coefb, beB.y, esc * tB.y);
            wB.z = fmaf(coefb, beB.z, esc * tB.z);
            wB.w = fmaf(coefb, beB.w, esc * tB.w);
            float nu  = fminf(rre * rq, 32.f);       // linner(w,w)=esc^2*re
            float rnu = fmaxf(nu, 1e-4f);
            float ex  = __expf(rnu);
            float exi = __expf(-rnu);
            float ch  = 0.5f * (ex + exi);
            float shn = 0.5f * (ex - exi) / rnu;
            float4 oA, oB;
            oA.x = fmaf(ch, beA.x, shn * wA.x);
            oA.y = fmaf(ch, beA.y, shn * wA.y);
            oA.z = fmaf(ch, beA.z, shn * wA.z);
            oA.w = fmaf(ch, beA.w, shn * wA.w);
            oB.x = fmaf(ch, beB.x, shn * wB.x);
            oB.y = fmaf(ch, beB.y, shn * wB.y);
            oB.z = fmaf(ch, beB.z, shn * wB.z);
            oB.w = fmaf(ch, beB.w, shn * wB.w);
            __stcs(&out4[bi], oA);
            __stcs(&out4[bi + 16u], oB);
        }
    }
}

extern "C" void kernel_launch(void* const* d_in, const int* in_sizes, int n_in,
                              void* d_out, int out_size) {
    const float4* x  = (const float4*)d_in[0];
    const float4* ga = (const float4*)d_in[1];
    const float4* be = (const float4*)d_in[2];
    float4* out = (float4*)d_out;
    (void)in_sizes; (void)n_in; (void)out_size;

    k_sumS<<<BB * CHUNKS, 256>>>(x);
    k_centroid<<<1, 1024>>>();
    k_stats<<<GRID_STATS, 256>>>(x);
    k_final<<<GRID_FIN, 256>>>(x, ga, be, out);
}